// round 1
// baseline (speedup 1.0000x reference)
#include <cuda_runtime.h>
#include <math.h>

#define E   512
#define HH  1536
#define SS  32
#define TT  48
#define NSZ 4

// Persistent state (device globals are the sanctioned scratch mechanism).
__device__ float g_x[E];
__device__ float g_h1[2][HH];
__device__ float g_c1[HH];
__device__ float g_h2[2][HH];
__device__ float g_c2[HH];

__device__ __forceinline__ float sigmoidf(float x) {
    return 1.0f / (1.0f + expf(-x));
}

__global__ void init_kernel(const int* __restrict__ input_id,
                            const float* __restrict__ emb) {
    int tid = threadIdx.x;  // 512 threads
    for (int i = tid; i < HH; i += 512) {
        g_h1[0][i] = 0.0f;
        g_c1[i]    = 0.0f;
        g_h2[0][i] = 0.0f;
        g_c2[i]    = 0.0f;
    }
    int id = *input_id;
    g_x[tid] = emb[(size_t)id * E + tid];
}

// One block per hidden unit; 4 warps = 4 gates (i,f,g,o).
__global__ void __launch_bounds__(128, 8)
cell1_kernel(const float* __restrict__ Wih, const float* __restrict__ Whh,
             const float* __restrict__ bih, const float* __restrict__ bhh,
             int p) {
    __shared__ float xh[E + HH];   // [x ; h1_old]
    __shared__ float gsh[4];
    int tid  = threadIdx.x;
    int unit = blockIdx.x;

    for (int i = tid; i < E;  i += 128) xh[i]     = g_x[i];
    for (int i = tid; i < HH; i += 128) xh[E + i] = g_h1[p][i];
    __syncthreads();

    int warp = tid >> 5, lane = tid & 31;
    int row = warp * HH + unit;   // gate row
    const float4* w1 = (const float4*)(Wih + (size_t)row * E);
    const float4* w2 = (const float4*)(Whh + (size_t)row * HH);
    const float4* xv = (const float4*)xh;
    const float4* hv = (const float4*)(xh + E);

    float acc = 0.0f;
    #pragma unroll
    for (int k = lane; k < E / 4; k += 32) {      // 4 iters/lane
        float4 a = w1[k], b = xv[k];
        acc += a.x * b.x + a.y * b.y + a.z * b.z + a.w * b.w;
    }
    #pragma unroll
    for (int k = lane; k < HH / 4; k += 32) {     // 12 iters/lane
        float4 a = w2[k], b = hv[k];
        acc += a.x * b.x + a.y * b.y + a.z * b.z + a.w * b.w;
    }
    #pragma unroll
    for (int o = 16; o; o >>= 1) acc += __shfl_down_sync(0xffffffffu, acc, o);
    if (lane == 0) gsh[warp] = acc + bih[row] + bhh[row];
    __syncthreads();

    if (tid == 0) {
        float gi = gsh[0], gf = gsh[1], gg = gsh[2], go = gsh[3];
        float c  = g_c1[unit];
        float cn = sigmoidf(gf) * c + sigmoidf(gi) * tanhf(gg);
        g_c1[unit]        = cn;
        g_h1[1 - p][unit] = sigmoidf(go) * tanhf(cn);
    }
}

__global__ void __launch_bounds__(128, 8)
cell2_kernel(const float* __restrict__ Wih, const float* __restrict__ Whh,
             const float* __restrict__ bih, const float* __restrict__ bhh,
             int p) {
    __shared__ float h1s[HH];
    __shared__ float h2s[HH];
    __shared__ float gsh[4];
    int tid  = threadIdx.x;
    int unit = blockIdx.x;

    for (int i = tid; i < HH; i += 128) {
        h1s[i] = g_h1[1 - p][i];   // fresh h1 from cell1
        h2s[i] = g_h2[p][i];       // old h2
    }
    __syncthreads();

    int warp = tid >> 5, lane = tid & 31;
    int row = warp * HH + unit;
    const float4* w1 = (const float4*)(Wih + (size_t)row * HH);
    const float4* w2 = (const float4*)(Whh + (size_t)row * HH);
    const float4* xv = (const float4*)h1s;
    const float4* hv = (const float4*)h2s;

    float acc = 0.0f;
    #pragma unroll
    for (int k = lane; k < HH / 4; k += 32) {
        float4 a = w1[k], b = xv[k];
        acc += a.x * b.x + a.y * b.y + a.z * b.z + a.w * b.w;
    }
    #pragma unroll
    for (int k = lane; k < HH / 4; k += 32) {
        float4 a = w2[k], b = hv[k];
        acc += a.x * b.x + a.y * b.y + a.z * b.z + a.w * b.w;
    }
    #pragma unroll
    for (int o = 16; o; o >>= 1) acc += __shfl_down_sync(0xffffffffu, acc, o);
    if (lane == 0) gsh[warp] = acc + bih[row] + bhh[row];
    __syncthreads();

    if (tid == 0) {
        float gi = gsh[0], gf = gsh[1], gg = gsh[2], go = gsh[3];
        float c  = g_c2[unit];
        float cn = sigmoidf(gf) * c + sigmoidf(gi) * tanhf(gg);
        g_c2[unit]        = cn;
        g_h2[1 - p][unit] = sigmoidf(go) * tanhf(cn);
    }
}

// Single block: logits + exact log_softmax + argmax + next-x fetch.
__global__ void __launch_bounds__(256, 1)
head_kernel(const float* __restrict__ Wout, const float* __restrict__ bout,
            const float* __restrict__ emb, float* __restrict__ out,
            int t, int p) {
    __shared__ float h2s[HH];
    __shared__ float logits[SS];
    __shared__ int   s_emb;
    int tid = threadIdx.x;  // 256

    for (int i = tid; i < HH; i += 256) h2s[i] = g_h2[1 - p][i];
    __syncthreads();

    int warp = tid >> 5, lane = tid & 31;  // 8 warps, 4 rows each
    const float4* hv = (const float4*)h2s;
    for (int s = warp * 4; s < warp * 4 + 4; s++) {
        const float4* w = (const float4*)(Wout + ((size_t)t * SS + s) * HH);
        float acc = 0.0f;
        #pragma unroll
        for (int k = lane; k < HH / 4; k += 32) {
            float4 a = w[k], b = hv[k];
            acc += a.x * b.x + a.y * b.y + a.z * b.z + a.w * b.w;
        }
        #pragma unroll
        for (int o = 16; o; o >>= 1) acc += __shfl_down_sync(0xffffffffu, acc, o);
        if (lane == 0) logits[s] = acc + bout[t * SS + s];
    }
    __syncthreads();

    if (warp == 0) {  // lane < 32 covers all S values
        float v = logits[lane];
        float m = v;
        #pragma unroll
        for (int o = 16; o; o >>= 1) m = fmaxf(m, __shfl_xor_sync(0xffffffffu, m, o));
        float e  = expf(v - m);
        float se = e;
        #pragma unroll
        for (int o = 16; o; o >>= 1) se += __shfl_xor_sync(0xffffffffu, se, o);
        float lse = m + logf(se);
        out[t * SS + lane] = v - lse;

        // argmax with first-index tie-break (matches jnp.argmax)
        float bv = v;
        int   bi = lane;
        #pragma unroll
        for (int o = 16; o; o >>= 1) {
            float ov = __shfl_xor_sync(0xffffffffu, bv, o);
            int   oi = __shfl_xor_sync(0xffffffffu, bi, o);
            if (ov > bv || (ov == bv && oi < bi)) { bv = ov; bi = oi; }
        }
        if (lane == 0) s_emb = (t % NSZ) * SS + bi;
    }
    __syncthreads();

    int eid = s_emb;
    for (int i = tid; i < E; i += 256)
        g_x[i] = emb[(size_t)eid * E + i];
}

extern "C" void kernel_launch(void* const* d_in, const int* in_sizes, int n_in,
                              void* d_out, int out_size) {
    const int*   input_id = (const int*)  d_in[0];
    const float* emb      = (const float*)d_in[1];
    const float* W_ih1    = (const float*)d_in[2];
    const float* W_hh1    = (const float*)d_in[3];
    const float* b_ih1    = (const float*)d_in[4];
    const float* b_hh1    = (const float*)d_in[5];
    const float* W_ih2    = (const float*)d_in[6];
    const float* W_hh2    = (const float*)d_in[7];
    const float* b_ih2    = (const float*)d_in[8];
    const float* b_hh2    = (const float*)d_in[9];
    const float* W_out    = (const float*)d_in[10];
    const float* b_out    = (const float*)d_in[11];
    float* out = (float*)d_out;

    init_kernel<<<1, 512>>>(input_id, emb);
    for (int t = 0; t < TT; t++) {
        int p = t & 1;
        cell1_kernel<<<HH, 128>>>(W_ih1, W_hh1, b_ih1, b_hh1, p);
        cell2_kernel<<<HH, 128>>>(W_ih2, W_hh2, b_ih2, b_hh2, p);
        head_kernel<<<1, 256>>>(W_out, b_out, emb, out, t, p);
    }
}

// round 2
// speedup vs baseline: 1.2742x; 1.2742x over previous
#include <cuda_runtime.h>
#include <math.h>

#define E    512
#define HH   1536
#define G4   6144      // 4*HH gate rows
#define SS   32
#define TT   48
#define NV   128       // embedding rows
#define NB   96        // persistent blocks (co-resident, <=148 SMs)
#define NT   1024
#define UPB  16        // units per block = HH/NB

// ---------------- persistent device state ----------------
__device__ float    g_xproj[NV * G4];   // W_ih1@emb[v] + b_ih1 + b_hh1
__device__ float    g_b2sum[G4];        // b_ih2 + b_hh2
__device__ float    g_h1[2][HH];
__device__ float    g_c1[HH];
__device__ float    g_h2[2][HH];
__device__ float    g_c2[HH];
__device__ unsigned g_bar;

__device__ __forceinline__ float sigm(float x) { return 1.0f / (1.0f + expf(-x)); }

__device__ __forceinline__ float warpsum(float v) {
    #pragma unroll
    for (int o = 16; o; o >>= 1) v += __shfl_down_sync(0xffffffffu, v, o);
    return v;
}

// dot of one 1536-long weight row (global) with an smem vector; per-lane partial
__device__ __forceinline__ float dot1536(const float* __restrict__ wrow,
                                         const float* __restrict__ sv, int lane) {
    const float4* w4 = (const float4*)wrow;
    const float4* v4 = (const float4*)sv;
    float acc = 0.f;
    #pragma unroll
    for (int j = 0; j < 12; j++) {
        float4 a = __ldg(&w4[lane + 32 * j]);
        float4 b = v4[lane + 32 * j];
        acc = fmaf(a.x, b.x, acc);
        acc = fmaf(a.y, b.y, acc);
        acc = fmaf(a.z, b.z, acc);
        acc = fmaf(a.w, b.w, acc);
    }
    return acc;
}

// grid-wide barrier: cumulative counter, reset by init kernel each launch
__device__ __forceinline__ void grid_sync(unsigned target) {
    __syncthreads();
    if (threadIdx.x == 0) {
        __threadfence();
        atomicAdd(&g_bar, 1u);
        while (*(volatile unsigned*)&g_bar < target) { }
        __threadfence();
    }
    __syncthreads();
}

// ---------------- init: zero state + fused bias ----------------
__global__ void init_kernel(const float* __restrict__ b_ih2,
                            const float* __restrict__ b_hh2) {
    int tid = threadIdx.x;  // 1024
    if (tid == 0) g_bar = 0u;
    for (int i = tid; i < HH; i += NT) {
        g_h2[1][i] = 0.0f;
        g_c2[i]    = 0.0f;
    }
    for (int i = tid; i < G4; i += NT)
        g_b2sum[i] = b_ih2[i] + b_hh2[i];
}

// ---------------- precompute xproj = W_ih1 @ emb^T + biases ----------------
__global__ void __launch_bounds__(512)
xproj_kernel(const float* __restrict__ Wih1,
             const float* __restrict__ bih1, const float* __restrict__ bhh1,
             const float* __restrict__ emb) {
    __shared__ __align__(16) float W[16 * E];   // 32 KB: 16 rows of W_ih1
    int b   = blockIdx.x;                        // rows b*16 .. b*16+15
    int tid = threadIdx.x;
    for (int i = tid; i < 16 * E; i += 512)
        W[i] = Wih1[(size_t)b * 16 * E + i];
    __syncthreads();

    // 16 rows x 128 embeddings = 2048 outputs; 4 per thread
    for (int o = tid; o < 16 * NV; o += 512) {
        int r = o & 15;        // local row
        int v = o >> 4;        // embedding id
        const float4* ev = (const float4*)(emb + (size_t)v * E);
        const float4* wr = (const float4*)(W + r * E);
        float acc = 0.f;
        #pragma unroll 4
        for (int k = 0; k < E / 4; k++) {
            float4 a = wr[k], c = ev[k];
            acc = fmaf(a.x, c.x, acc);
            acc = fmaf(a.y, c.y, acc);
            acc = fmaf(a.z, c.z, acc);
            acc = fmaf(a.w, c.w, acc);
        }
        int row = b * 16 + r;
        g_xproj[(size_t)v * G4 + row] = acc + bih1[row] + bhh1[row];
    }
}

// ---------------- the persistent controller kernel ----------------
__global__ void __launch_bounds__(NT, 1)
nas_persist(const int*   __restrict__ input_id,
            const float* __restrict__ Whh1,
            const float* __restrict__ Wih2,
            const float* __restrict__ Whh2,
            const float* __restrict__ Wout,
            const float* __restrict__ bout,
            float* __restrict__ out) {
    __shared__ __align__(16) float sA[HH];   // h1 (current)
    __shared__ __align__(16) float sB[HH];   // h2 (old / new)
    __shared__ float sG[64];                 // gates [gate][16 units]
    __shared__ float sL[SS];
    __shared__ int   sId;

    const int tid  = threadIdx.x;
    const int w    = tid >> 5;
    const int lane = tid & 31;
    const int b    = blockIdx.x;
    const int u0   = b * UPB;
    unsigned epoch = 0;

    // ---- Phase0: h1[0], c1 from xproj[input_id] (h1_prev = 0, c1_prev = 0)
    {
        int id0 = *input_id;
        if (tid < UPB) {
            int u = u0 + tid;
            const float* xp = g_xproj + (size_t)id0 * G4;
            float gi = xp[u], gf = xp[HH + u], gg = xp[2 * HH + u], go = xp[3 * HH + u];
            (void)gf;
            float cn = sigm(gi) * tanhf(gg);      // c_old = 0
            g_c1[u]     = cn;
            g_h1[0][u]  = sigm(go) * tanhf(cn);
        }
    }
    grid_sync(++epoch * NB);

    for (int t = 0; t < TT; t++) {
        const int pc = t & 1;   // h1[t] buffer; h2 old = pc^1, h2 new = pc

        // ======== Phase1: cell2 gates + finalize h2 ========
        for (int i = tid; i < HH; i += NT) {
            sA[i] = g_h1[pc][i];
            sB[i] = g_h2[pc ^ 1][i];
        }
        __syncthreads();

        #pragma unroll
        for (int q = 0; q < 2; q++) {
            int l    = 2 * w + q;
            int gate = l >> 4, ul = l & 15;
            int grow = gate * HH + u0 + ul;
            float acc = dot1536(Wih2 + (size_t)grow * HH, sA, lane)
                      + dot1536(Whh2 + (size_t)grow * HH, sB, lane);
            acc = warpsum(acc);
            if (lane == 0) sG[l] = acc + g_b2sum[grow];
        }
        __syncthreads();

        if (tid < UPB) {
            int u = u0 + tid;
            float gi = sG[tid], gf = sG[16 + tid], gg = sG[32 + tid], go = sG[48 + tid];
            float c  = g_c2[u];
            float cn = sigm(gf) * c + sigm(gi) * tanhf(gg);
            g_c2[u]      = cn;
            g_h2[pc][u]  = sigm(go) * tanhf(cn);
        }
        grid_sync(++epoch * NB);

        // ======== Phase2: head (redundant per block) + W_hh1@h1 + finalize h1 ========
        for (int i = tid; i < HH; i += NT) sB[i] = g_h2[pc][i];  // sA still holds h1[t]
        __syncthreads();

        // head logit: warp w -> choice s = w
        {
            float acc = dot1536(Wout + ((size_t)t * SS + w) * HH, sB, lane);
            acc = warpsum(acc);
            if (lane == 0) sL[w] = acc + bout[t * SS + w];
        }
        // next-step cell1 hidden contribution
        #pragma unroll
        for (int q = 0; q < 2; q++) {
            int l    = 2 * w + q;
            int gate = l >> 4, ul = l & 15;
            int grow = gate * HH + u0 + ul;
            float acc = dot1536(Whh1 + (size_t)grow * HH, sA, lane);
            acc = warpsum(acc);
            if (lane == 0) sG[l] = acc;
        }
        __syncthreads();

        if (w == 0) {   // exact log_softmax + argmax (first-index tie-break)
            float v = sL[lane];
            float m = v;
            #pragma unroll
            for (int o = 16; o; o >>= 1) m = fmaxf(m, __shfl_xor_sync(0xffffffffu, m, o));
            float e = expf(v - m);
            float se = e;
            #pragma unroll
            for (int o = 16; o; o >>= 1) se += __shfl_xor_sync(0xffffffffu, se, o);
            float lse = m + logf(se);
            if (b == 0) out[t * SS + lane] = v - lse;

            float bv = v; int bi = lane;
            #pragma unroll
            for (int o = 16; o; o >>= 1) {
                float ov = __shfl_xor_sync(0xffffffffu, bv, o);
                int   oi = __shfl_xor_sync(0xffffffffu, bi, o);
                if (ov > bv || (ov == bv && oi < bi)) { bv = ov; bi = oi; }
            }
            if (lane == 0) sId = (t & 3) * SS + bi;   // (t % 4)*32 + pred
        }
        __syncthreads();

        if (tid < UPB) {
            int u = u0 + tid;
            const float* xp = g_xproj + (size_t)sId * G4;
            float gi = sG[tid]      + xp[u];
            float gf = sG[16 + tid] + xp[HH + u];
            float gg = sG[32 + tid] + xp[2 * HH + u];
            float go = sG[48 + tid] + xp[3 * HH + u];
            float c  = g_c1[u];
            float cn = sigm(gf) * c + sigm(gi) * tanhf(gg);
            g_c1[u]          = cn;
            g_h1[pc ^ 1][u]  = sigm(go) * tanhf(cn);
        }
        grid_sync(++epoch * NB);
    }
}

extern "C" void kernel_launch(void* const* d_in, const int* in_sizes, int n_in,
                              void* d_out, int out_size) {
    const int*   input_id = (const int*)  d_in[0];
    const float* emb      = (const float*)d_in[1];
    const float* W_ih1    = (const float*)d_in[2];
    const float* W_hh1    = (const float*)d_in[3];
    const float* b_ih1    = (const float*)d_in[4];
    const float* b_hh1    = (const float*)d_in[5];
    const float* W_ih2    = (const float*)d_in[6];
    const float* W_hh2    = (const float*)d_in[7];
    const float* b_ih2    = (const float*)d_in[8];
    const float* b_hh2    = (const float*)d_in[9];
    const float* W_out    = (const float*)d_in[10];
    const float* b_out    = (const float*)d_in[11];
    float* out = (float*)d_out;

    init_kernel<<<1, NT>>>(b_ih2, b_hh2);
    xproj_kernel<<<G4 / 16, 512>>>(W_ih1, b_ih1, b_hh1, emb);
    nas_persist<<<NB, NT>>>(input_id, W_hh1, W_ih2, W_hh2, W_out, b_out, out);
}

// round 3
// speedup vs baseline: 1.4729x; 1.1559x over previous
#include <cuda_runtime.h>
#include <cuda_bf16.h>
#include <math.h>

#define E    512
#define HH   1536
#define G4   6144      // 4*HH gate rows
#define SS   32
#define TT   48
#define NV   128       // embedding rows
#define NB   96        // persistent blocks
#define NT   1024
#define UPB  16        // units per block = HH/NB
#define WELEM (G4 * HH)  // elements per square-ish weight matrix

// ---------------- persistent device state ----------------
__device__ float          g_xproj[NV * G4];   // W_ih1@emb[v] + b_ih1 + b_hh1
__device__ float          g_b2sum[G4];        // b_ih2 + b_hh2
__device__ __nv_bfloat16  g_whh1[WELEM];      // bf16 copies (L2-resident working set)
__device__ __nv_bfloat16  g_wih2[WELEM];
__device__ __nv_bfloat16  g_whh2[WELEM];
__device__ float          g_h1[2][HH];
__device__ float          g_c1[HH];
__device__ float          g_h2[2][HH];
__device__ float          g_c2[HH];
__device__ unsigned       g_bar;

__device__ __forceinline__ float sigm(float x) { return 1.0f / (1.0f + expf(-x)); }

__device__ __forceinline__ float warpsum(float v) {
    #pragma unroll
    for (int o = 16; o; o >>= 1) v += __shfl_down_sync(0xffffffffu, v, o);
    return v;
}

// fp32 row dot (head): 12 float4 per lane
__device__ __forceinline__ float dot1536_f32(const float* __restrict__ wrow,
                                             const float* __restrict__ sv, int lane) {
    const float4* w4 = (const float4*)wrow;
    const float4* v4 = (const float4*)sv;
    float acc = 0.f;
    #pragma unroll
    for (int j = 0; j < 12; j++) {
        float4 a = __ldg(&w4[lane + 32 * j]);
        float4 b = v4[lane + 32 * j];
        acc = fmaf(a.x, b.x, acc);
        acc = fmaf(a.y, b.y, acc);
        acc = fmaf(a.z, b.z, acc);
        acc = fmaf(a.w, b.w, acc);
    }
    return acc;
}

// bf16 row dot, fp32 accumulate: 6 uint4 (=48 bf16) per lane
__device__ __forceinline__ float dot1536_bf16(const __nv_bfloat16* __restrict__ wrow,
                                              const float* __restrict__ sv, int lane) {
    const uint4*  w4 = (const uint4*)wrow;
    float acc = 0.f;
    #pragma unroll
    for (int j = 0; j < 6; j++) {
        int seg = lane + 32 * j;               // 8 elements per seg
        uint4 a = __ldg(&w4[seg]);
        const float4* v = (const float4*)(sv + seg * 8);
        float4 v0 = v[0], v1 = v[1];
        float2 p;
        p = __bfloat1622float2(*(const __nv_bfloat162*)&a.x);
        acc = fmaf(p.x, v0.x, acc); acc = fmaf(p.y, v0.y, acc);
        p = __bfloat1622float2(*(const __nv_bfloat162*)&a.y);
        acc = fmaf(p.x, v0.z, acc); acc = fmaf(p.y, v0.w, acc);
        p = __bfloat1622float2(*(const __nv_bfloat162*)&a.z);
        acc = fmaf(p.x, v1.x, acc); acc = fmaf(p.y, v1.y, acc);
        p = __bfloat1622float2(*(const __nv_bfloat162*)&a.w);
        acc = fmaf(p.x, v1.z, acc); acc = fmaf(p.y, v1.w, acc);
    }
    return acc;
}

// grid-wide barrier: cumulative counter, reset each launch by init kernel
__device__ __forceinline__ void grid_sync(unsigned target) {
    __syncthreads();
    if (threadIdx.x == 0) {
        __threadfence();
        atomicAdd(&g_bar, 1u);
        while (*(volatile unsigned*)&g_bar < target) { }
        __threadfence();
    }
    __syncthreads();
}

// ---------------- init: zero state + fused bias ----------------
__global__ void init_kernel(const float* __restrict__ b_ih2,
                            const float* __restrict__ b_hh2) {
    int tid = threadIdx.x;  // 1024
    if (tid == 0) g_bar = 0u;
    for (int i = tid; i < HH; i += NT) {
        g_h2[1][i] = 0.0f;
        g_c2[i]    = 0.0f;
    }
    for (int i = tid; i < G4; i += NT)
        g_b2sum[i] = b_ih2[i] + b_hh2[i];
}

// ---------------- fp32 -> bf16 weight conversion ----------------
__global__ void __launch_bounds__(256)
cvt_kernel(const float* __restrict__ src, __nv_bfloat16* __restrict__ dst) {
    // 8 elements per thread, WELEM = 9,437,184
    int i = (blockIdx.x * 256 + threadIdx.x) * 8;
    if (i >= WELEM) return;
    float4 a = *(const float4*)(src + i);
    float4 b = *(const float4*)(src + i + 4);
    __nv_bfloat162 r0 = __floats2bfloat162_rn(a.x, a.y);
    __nv_bfloat162 r1 = __floats2bfloat162_rn(a.z, a.w);
    __nv_bfloat162 r2 = __floats2bfloat162_rn(b.x, b.y);
    __nv_bfloat162 r3 = __floats2bfloat162_rn(b.z, b.w);
    uint4 o;
    o.x = *(const unsigned*)&r0; o.y = *(const unsigned*)&r1;
    o.z = *(const unsigned*)&r2; o.w = *(const unsigned*)&r3;
    *(uint4*)(dst + i) = o;
}

// ---------------- precompute xproj = W_ih1 @ emb^T + biases ----------------
__global__ void __launch_bounds__(512)
xproj_kernel(const float* __restrict__ Wih1,
             const float* __restrict__ bih1, const float* __restrict__ bhh1,
             const float* __restrict__ emb) {
    __shared__ __align__(16) float W[16 * E];   // 32 KB: 16 rows of W_ih1
    int b   = blockIdx.x;                        // rows b*16 .. b*16+15
    int tid = threadIdx.x;
    for (int i = tid; i < 16 * E; i += 512)
        W[i] = Wih1[(size_t)b * 16 * E + i];
    __syncthreads();

    for (int o = tid; o < 16 * NV; o += 512) {
        int r = o & 15;
        int v = o >> 4;
        const float4* ev = (const float4*)(emb + (size_t)v * E);
        const float4* wr = (const float4*)(W + r * E);
        float acc = 0.f;
        #pragma unroll 4
        for (int k = 0; k < E / 4; k++) {
            float4 a = wr[k], c = ev[k];
            acc = fmaf(a.x, c.x, acc);
            acc = fmaf(a.y, c.y, acc);
            acc = fmaf(a.z, c.z, acc);
            acc = fmaf(a.w, c.w, acc);
        }
        int row = b * 16 + r;
        g_xproj[(size_t)v * G4 + row] = acc + bih1[row] + bhh1[row];
    }
}

// ---------------- the persistent controller kernel ----------------
__global__ void __launch_bounds__(NT, 1)
nas_persist(const int*   __restrict__ input_id,
            const float* __restrict__ Wout,
            const float* __restrict__ bout,
            float* __restrict__ out) {
    __shared__ __align__(16) float sA[HH];   // h1 (current)
    __shared__ __align__(16) float sB[HH];   // h2 (old / new)
    __shared__ float sG[64];                 // gates [gate][16 units]
    __shared__ float sL[SS];
    __shared__ int   sId;

    const int tid  = threadIdx.x;
    const int w    = tid >> 5;
    const int lane = tid & 31;
    const int b    = blockIdx.x;
    const int u0   = b * UPB;
    unsigned epoch = 0;

    // ---- Phase0: h1[0], c1 from xproj[input_id] (h1_prev = 0, c1_prev = 0)
    {
        int id0 = *input_id;
        if (tid < UPB) {
            int u = u0 + tid;
            const float* xp = g_xproj + (size_t)id0 * G4;
            float gi = xp[u], gg = xp[2 * HH + u], go = xp[3 * HH + u];
            float cn = sigm(gi) * tanhf(gg);      // c_old = 0
            g_c1[u]     = cn;
            g_h1[0][u]  = sigm(go) * tanhf(cn);
        }
    }
    grid_sync(++epoch * NB);

    for (int t = 0; t < TT; t++) {
        const int pc = t & 1;   // h1[t] buffer; h2 old = pc^1, h2 new = pc

        // ======== Phase1: cell2 gates + finalize h2 ========
        for (int i = tid; i < HH; i += NT) {
            sA[i] = g_h1[pc][i];
            sB[i] = g_h2[pc ^ 1][i];
        }
        __syncthreads();

        #pragma unroll
        for (int q = 0; q < 2; q++) {
            int l    = 2 * w + q;
            int gate = l >> 4, ul = l & 15;
            int grow = gate * HH + u0 + ul;
            float acc = dot1536_bf16(g_wih2 + (size_t)grow * HH, sA, lane)
                      + dot1536_bf16(g_whh2 + (size_t)grow * HH, sB, lane);
            acc = warpsum(acc);
            if (lane == 0) sG[l] = acc + g_b2sum[grow];
        }
        __syncthreads();

        if (tid < UPB) {
            int u = u0 + tid;
            float gi = sG[tid], gf = sG[16 + tid], gg = sG[32 + tid], go = sG[48 + tid];
            float c  = g_c2[u];
            float cn = sigm(gf) * c + sigm(gi) * tanhf(gg);
            g_c2[u]      = cn;
            g_h2[pc][u]  = sigm(go) * tanhf(cn);
        }
        grid_sync(++epoch * NB);

        // ======== Phase2: head (redundant per block, fp32) + W_hh1@h1 + finalize h1 ========
        for (int i = tid; i < HH; i += NT) sB[i] = g_h2[pc][i];  // sA still holds h1[t]
        __syncthreads();

        // head logit: warp w -> choice s = w
        {
            float acc = dot1536_f32(Wout + ((size_t)t * SS + w) * HH, sB, lane);
            acc = warpsum(acc);
            if (lane == 0) sL[w] = acc + bout[t * SS + w];
        }
        // next-step cell1 hidden contribution
        #pragma unroll
        for (int q = 0; q < 2; q++) {
            int l    = 2 * w + q;
            int gate = l >> 4, ul = l & 15;
            int grow = gate * HH + u0 + ul;
            float acc = dot1536_bf16(g_whh1 + (size_t)grow * HH, sA, lane);
            acc = warpsum(acc);
            if (lane == 0) sG[l] = acc;
        }
        __syncthreads();

        if (w == 0) {   // exact log_softmax + argmax (first-index tie-break)
            float v = sL[lane];
            float m = v;
            #pragma unroll
            for (int o = 16; o; o >>= 1) m = fmaxf(m, __shfl_xor_sync(0xffffffffu, m, o));
            float e = expf(v - m);
            float se = e;
            #pragma unroll
            for (int o = 16; o; o >>= 1) se += __shfl_xor_sync(0xffffffffu, se, o);
            float lse = m + logf(se);
            if (b == 0) out[t * SS + lane] = v - lse;

            float bv = v; int bi = lane;
            #pragma unroll
            for (int o = 16; o; o >>= 1) {
                float ov = __shfl_xor_sync(0xffffffffu, bv, o);
                int   oi = __shfl_xor_sync(0xffffffffu, bi, o);
                if (ov > bv || (ov == bv && oi < bi)) { bv = ov; bi = oi; }
            }
            if (lane == 0) sId = (t & 3) * SS + bi;   // (t % 4)*32 + pred
        }
        __syncthreads();

        if (tid < UPB) {
            int u = u0 + tid;
            const float* xp = g_xproj + (size_t)sId * G4;
            float gi = sG[tid]      + xp[u];
            float gf = sG[16 + tid] + xp[HH + u];
            float gg = sG[32 + tid] + xp[2 * HH + u];
            float go = sG[48 + tid] + xp[3 * HH + u];
            float c  = g_c1[u];
            float cn = sigm(gf) * c + sigm(gi) * tanhf(gg);
            g_c1[u]          = cn;
            g_h1[pc ^ 1][u]  = sigm(go) * tanhf(cn);
        }
        grid_sync(++epoch * NB);
    }
}

extern "C" void kernel_launch(void* const* d_in, const int* in_sizes, int n_in,
                              void* d_out, int out_size) {
    const int*   input_id = (const int*)  d_in[0];
    const float* emb      = (const float*)d_in[1];
    const float* W_ih1    = (const float*)d_in[2];
    const float* W_hh1    = (const float*)d_in[3];
    const float* b_ih1    = (const float*)d_in[4];
    const float* b_hh1    = (const float*)d_in[5];
    const float* W_ih2    = (const float*)d_in[6];
    const float* W_hh2    = (const float*)d_in[7];
    const float* b_ih2    = (const float*)d_in[8];
    const float* b_hh2    = (const float*)d_in[9];
    const float* W_out    = (const float*)d_in[10];
    const float* b_out    = (const float*)d_in[11];
    float* out = (float*)d_out;

    __nv_bfloat16* whh1_d; cudaGetSymbolAddress((void**)&whh1_d, g_whh1);
    __nv_bfloat16* wih2_d; cudaGetSymbolAddress((void**)&wih2_d, g_wih2);
    __nv_bfloat16* whh2_d; cudaGetSymbolAddress((void**)&whh2_d, g_whh2);

    const int cvt_blocks = (WELEM / 8 + 255) / 256;
    init_kernel<<<1, NT>>>(b_ih2, b_hh2);
    cvt_kernel<<<cvt_blocks, 256>>>(W_hh1, whh1_d);
    cvt_kernel<<<cvt_blocks, 256>>>(W_ih2, wih2_d);
    cvt_kernel<<<cvt_blocks, 256>>>(W_hh2, whh2_d);
    xproj_kernel<<<G4 / 16, 512>>>(W_ih1, b_ih1, b_hh1, emb);
    nas_persist<<<NB, NT>>>(input_id, W_out, b_out, out);
}

// round 4
// speedup vs baseline: 1.7022x; 1.1557x over previous
#include <cuda_runtime.h>
#include <cuda_bf16.h>
#include <math.h>

#define E    512
#define HH   1536
#define G4   6144
#define SS   32
#define TT   48
#define NV   128
#define NB   128       // persistent blocks (1 per SM, <=148)
#define NT   512
#define UPB  12        // units per block = HH/NB
#define WELEM (G4 * HH)

// ---------------- persistent device state ----------------
__device__ float          g_xproj[NV * G4];     // W_ih1@emb[v] + b_ih1 + b_hh1
__device__ float          g_b2sum[G4];          // b_ih2 + b_hh2
__device__ __nv_bfloat16  g_w2cat[(size_t)G4 * 2 * HH];  // [W_ih2 | W_hh2] rows of 3072
__device__ __nv_bfloat16  g_whh1[WELEM];
__device__ float          g_c1[2][HH];
__device__ float          g_c2[HH];
__device__ float          g_h2[2][HH];
__device__ float          g_g1[G4];             // W_hh1 @ h1(t) partial gates
__device__ float          g_logits[SS];
__device__ unsigned       g_bar;

// fast activations (cell path only; output path uses exact expf/logf)
__device__ __forceinline__ float fsigm(float x) {
    return __fdividef(1.0f, 1.0f + __expf(-x));
}
__device__ __forceinline__ float ftanh(float x) {
    x = fminf(fmaxf(x, -15.0f), 15.0f);
    float e = __expf(2.0f * x);
    return __fdividef(e - 1.0f, e + 1.0f);
}

__device__ __forceinline__ float warpsum(float v) {
    #pragma unroll
    for (int o = 16; o; o >>= 1) v += __shfl_down_sync(0xffffffffu, v, o);
    return v;
}

// bf16 dot, fp32 accumulate; SEGS segments of 256 elems (8 per lane)
template<int SEGS>
__device__ __forceinline__ float dot_bf16(const __nv_bfloat16* __restrict__ wrow,
                                          const float* __restrict__ sv, int lane) {
    const uint4* w4 = (const uint4*)wrow;
    float acc = 0.f;
    #pragma unroll
    for (int j = 0; j < SEGS; j++) {
        int seg = lane + 32 * j;
        uint4 a = __ldg(&w4[seg]);
        const float4* v = (const float4*)(sv + seg * 8);
        float4 v0 = v[0], v1 = v[1];
        float2 p;
        p = __bfloat1622float2(*(const __nv_bfloat162*)&a.x);
        acc = fmaf(p.x, v0.x, acc); acc = fmaf(p.y, v0.y, acc);
        p = __bfloat1622float2(*(const __nv_bfloat162*)&a.y);
        acc = fmaf(p.x, v0.z, acc); acc = fmaf(p.y, v0.w, acc);
        p = __bfloat1622float2(*(const __nv_bfloat162*)&a.z);
        acc = fmaf(p.x, v1.x, acc); acc = fmaf(p.y, v1.y, acc);
        p = __bfloat1622float2(*(const __nv_bfloat162*)&a.w);
        acc = fmaf(p.x, v1.z, acc); acc = fmaf(p.y, v1.w, acc);
    }
    return acc;
}

__device__ __forceinline__ float dot1536_f32(const float* __restrict__ wrow,
                                             const float* __restrict__ sv, int lane) {
    const float4* w4 = (const float4*)wrow;
    const float4* v4 = (const float4*)sv;
    float acc = 0.f;
    #pragma unroll
    for (int j = 0; j < 12; j++) {
        float4 a = __ldg(&w4[lane + 32 * j]);
        float4 b = v4[lane + 32 * j];
        acc = fmaf(a.x, b.x, acc); acc = fmaf(a.y, b.y, acc);
        acc = fmaf(a.z, b.z, acc); acc = fmaf(a.w, b.w, acc);
    }
    return acc;
}

// grid-wide barrier: cumulative counter, release/acquire fenced
__device__ __forceinline__ void grid_sync(unsigned target) {
    __threadfence();
    __syncthreads();
    if (threadIdx.x == 0) {
        atomicAdd(&g_bar, 1u);
        while (*(volatile unsigned*)&g_bar < target) { }
        __threadfence();
    }
    __syncthreads();
}

// ---------------- init ----------------
__global__ void init_kernel(const float* __restrict__ b_ih2,
                            const float* __restrict__ b_hh2) {
    int tid = threadIdx.x;  // 1024
    if (tid == 0) g_bar = 0u;
    for (int i = tid; i < HH; i += 1024) g_c2[i] = 0.0f;
    for (int i = tid; i < G4; i += 1024) g_b2sum[i] = b_ih2[i] + b_hh2[i];
}

// ---------------- fp32 -> bf16 (optionally into concat layout) ----------------
__global__ void __launch_bounds__(256)
cvt_kernel(const float* __restrict__ src, __nv_bfloat16* __restrict__ dst,
           int dst_stride, int col_off) {
    unsigned i = (blockIdx.x * 256u + threadIdx.x) * 8u;
    if (i >= WELEM) return;
    unsigned row = i / HH, col = i % HH;
    float4 a = *(const float4*)(src + i);
    float4 b = *(const float4*)(src + i + 4);
    __nv_bfloat162 r0 = __floats2bfloat162_rn(a.x, a.y);
    __nv_bfloat162 r1 = __floats2bfloat162_rn(a.z, a.w);
    __nv_bfloat162 r2 = __floats2bfloat162_rn(b.x, b.y);
    __nv_bfloat162 r3 = __floats2bfloat162_rn(b.z, b.w);
    uint4 o;
    o.x = *(const unsigned*)&r0; o.y = *(const unsigned*)&r1;
    o.z = *(const unsigned*)&r2; o.w = *(const unsigned*)&r3;
    *(uint4*)(dst + (size_t)row * dst_stride + col_off + col) = o;
}

// ---------------- precompute xproj = W_ih1 @ emb^T + biases ----------------
__global__ void __launch_bounds__(512)
xproj_kernel(const float* __restrict__ Wih1,
             const float* __restrict__ bih1, const float* __restrict__ bhh1,
             const float* __restrict__ emb) {
    __shared__ __align__(16) float W[16 * E];
    int b   = blockIdx.x;
    int tid = threadIdx.x;
    for (int i = tid; i < 16 * E; i += 512)
        W[i] = Wih1[(size_t)b * 16 * E + i];
    __syncthreads();
    for (int o = tid; o < 16 * NV; o += 512) {
        int r = o & 15, v = o >> 4;
        const float4* ev = (const float4*)(emb + (size_t)v * E);
        const float4* wr = (const float4*)(W + r * E);
        float acc = 0.f;
        #pragma unroll 4
        for (int k = 0; k < E / 4; k++) {
            float4 a = wr[k], c = ev[k];
            acc = fmaf(a.x, c.x, acc); acc = fmaf(a.y, c.y, acc);
            acc = fmaf(a.z, c.z, acc); acc = fmaf(a.w, c.w, acc);
        }
        int row = b * 16 + r;
        g_xproj[(size_t)v * G4 + row] = acc + bih1[row] + bhh1[row];
    }
}

// ---------------- persistent controller ----------------
__global__ void __launch_bounds__(NT, 1)
nas_persist(const int*   __restrict__ input_id,
            const float* __restrict__ Wout,
            const float* __restrict__ bout,
            float* __restrict__ out) {
    __shared__ __align__(16) float sV[2 * HH];   // [h1(t) ; h2]
    __shared__ float sG[48];
    __shared__ int   sId;

    const int tid  = threadIdx.x;
    const int w    = tid >> 5;
    const int lane = tid & 31;
    const int b    = blockIdx.x;
    const int u0   = b * UPB;
    unsigned epoch = 0;

    for (int t = 0; t < TT; t++) {
        const int par = t & 1;

        // ===== P1: build h1(t) + stage h2(t-1); cell2 gates; finalize h2(t) =====
        if (t == 0) {
            int id0 = *input_id;
            const float* xp = g_xproj + (size_t)id0 * G4;
            for (int u = tid; u < HH; u += NT) {
                float gi = xp[u], gg = xp[2 * HH + u], go = xp[3 * HH + u];
                float cn = fsigm(gi) * ftanh(gg);            // c_old = 0
                sV[u] = fsigm(go) * ftanh(cn);
                if (u >= u0 && u < u0 + UPB) g_c1[1][u] = cn;
            }
            for (int i = tid; i < HH; i += NT) sV[HH + i] = 0.f;  // h2(-1)=0
        } else {
            // prefetch everything independent of sId
            float a0[3], a1[3], a2[3], a3[3], cc[3], hh[3];
            #pragma unroll
            for (int k = 0; k < 3; k++) {
                int u = tid + k * NT;
                a0[k] = g_g1[u];          a1[k] = g_g1[HH + u];
                a2[k] = g_g1[2 * HH + u]; a3[k] = g_g1[3 * HH + u];
                cc[k] = g_c1[par][u];
                hh[k] = g_h2[par ^ 1][u];
            }

            // warp 0: softmax/argmax of step t-1; block 0 writes out[t-1]
            if (w == 0) {
                float v = g_logits[lane];
                float m = v;
                #pragma unroll
                for (int o = 16; o; o >>= 1) m = fmaxf(m, __shfl_xor_sync(0xffffffffu, m, o));
                float e = expf(v - m), se = e;
                #pragma unroll
                for (int o = 16; o; o >>= 1) se += __shfl_xor_sync(0xffffffffu, se, o);
                float lse = m + logf(se);
                if (b == 0) out[(t - 1) * SS + lane] = v - lse;
                float bv = v; int bi = lane;
                #pragma unroll
                for (int o = 16; o; o >>= 1) {
                    float ov = __shfl_xor_sync(0xffffffffu, bv, o);
                    int   oi = __shfl_xor_sync(0xffffffffu, bi, o);
                    if (ov > bv || (ov == bv && oi < bi)) { bv = ov; bi = oi; }
                }
                if (lane == 0) sId = ((t - 1) & 3) * SS + bi;
            }
            __syncthreads();

            const float* xp = g_xproj + (size_t)sId * G4;
            #pragma unroll
            for (int k = 0; k < 3; k++) {
                int u = tid + k * NT;
                float gi = a0[k] + xp[u];
                float gf = a1[k] + xp[HH + u];
                float gg = a2[k] + xp[2 * HH + u];
                float go = a3[k] + xp[3 * HH + u];
                float cn = fsigm(gf) * cc[k] + fsigm(gi) * ftanh(gg);
                sV[u] = fsigm(go) * ftanh(cn);
                if (u >= u0 && u < u0 + UPB) g_c1[par ^ 1][u] = cn;
                sV[HH + u] = hh[k];
            }
        }
        __syncthreads();

        // cell2 gates: 3 concat rows (3072) per warp
        #pragma unroll
        for (int q = 0; q < 3; q++) {
            int l = 3 * w + q;             // 0..47
            int gate = l / 12, j = l % 12;
            int grow = gate * HH + u0 + j;
            float acc = dot_bf16<12>(g_w2cat + (size_t)grow * (2 * HH), sV, lane);
            acc = warpsum(acc);
            if (lane == 0) sG[l] = acc + g_b2sum[grow];
        }
        __syncthreads();

        if (tid < UPB) {
            int u = u0 + tid;
            float gi = sG[tid], gf = sG[12 + tid], gg = sG[24 + tid], go = sG[36 + tid];
            float c  = g_c2[u];
            float cn = fsigm(gf) * c + fsigm(gi) * ftanh(gg);
            g_c2[u]      = cn;
            g_h2[par][u] = fsigm(go) * ftanh(cn);
        }
        grid_sync(++epoch * NB);

        // ===== P2: g1 = W_hh1 @ h1(t) (distributed) + head logits =====
        for (int i = tid; i < HH; i += NT) sV[HH + i] = g_h2[par][i];
        __syncthreads();

        int wg = b * 16 + w;               // global warp id 0..2047
        #pragma unroll
        for (int q = 0; q < 3; q++) {
            int row = 3 * wg + q;          // 0..6143
            float acc = dot_bf16<6>(g_whh1 + (size_t)row * HH, sV, lane);
            acc = warpsum(acc);
            if (lane == 0) g_g1[row] = acc;
        }
        if (b < SS && w == 15) {           // one fp32 head row per block 0..31
            float acc = dot1536_f32(Wout + ((size_t)t * SS + b) * HH, sV + HH, lane);
            acc = warpsum(acc);
            if (lane == 0) g_logits[b] = acc + bout[t * SS + b];
        }
        grid_sync(++epoch * NB);
    }

    // epilogue: logp for t = 47
    if (b == 0 && w == 0) {
        float v = g_logits[lane];
        float m = v;
        #pragma unroll
        for (int o = 16; o; o >>= 1) m = fmaxf(m, __shfl_xor_sync(0xffffffffu, m, o));
        float e = expf(v - m), se = e;
        #pragma unroll
        for (int o = 16; o; o >>= 1) se += __shfl_xor_sync(0xffffffffu, se, o);
        float lse = m + logf(se);
        out[47 * SS + lane] = v - lse;
    }
}

extern "C" void kernel_launch(void* const* d_in, const int* in_sizes, int n_in,
                              void* d_out, int out_size) {
    const int*   input_id = (const int*)  d_in[0];
    const float* emb      = (const float*)d_in[1];
    const float* W_ih1    = (const float*)d_in[2];
    const float* W_hh1    = (const float*)d_in[3];
    const float* b_ih1    = (const float*)d_in[4];
    const float* b_hh1    = (const float*)d_in[5];
    const float* W_ih2    = (const float*)d_in[6];
    const float* W_hh2    = (const float*)d_in[7];
    const float* b_ih2    = (const float*)d_in[8];
    const float* b_hh2    = (const float*)d_in[9];
    const float* W_out    = (const float*)d_in[10];
    const float* b_out    = (const float*)d_in[11];
    float* out = (float*)d_out;

    __nv_bfloat16* w2cat_d; cudaGetSymbolAddress((void**)&w2cat_d, g_w2cat);
    __nv_bfloat16* whh1_d;  cudaGetSymbolAddress((void**)&whh1_d,  g_whh1);

    const int cvt_blocks = (WELEM / 8 + 255) / 256;
    init_kernel<<<1, 1024>>>(b_ih2, b_hh2);
    cvt_kernel<<<cvt_blocks, 256>>>(W_ih2, w2cat_d, 2 * HH, 0);
    cvt_kernel<<<cvt_blocks, 256>>>(W_hh2, w2cat_d, 2 * HH, HH);
    cvt_kernel<<<cvt_blocks, 256>>>(W_hh1, whh1_d, HH, 0);
    xproj_kernel<<<G4 / 16, 512>>>(W_ih1, b_ih1, b_hh1, emb);
    nas_persist<<<NB, NT>>>(input_id, W_out, b_out, out);
}

// round 5
// speedup vs baseline: 2.1044x; 1.2363x over previous
#include <cuda_runtime.h>
#include <cuda_bf16.h>
#include <math.h>

#define E    512
#define HH   1536
#define G4   6144
#define SS   32
#define TT   48
#define NV   128
#define NB   128       // persistent blocks (1/SM, <=148)
#define NT   512
#define UPB  12        // h2/c2 units per block
#define WELEM      (G4 * HH)
#define WOUT_ELEMS (TT * SS * HH)

// ---------------- persistent device state ----------------
__device__ float          g_xproj[NV * G4];            // W_ih1@emb[v] + b_ih1 + b_hh1
__device__ float          g_b2sum[G4];                 // b_ih2 + b_hh2
__device__ __nv_bfloat16  g_w2cat[(size_t)G4 * 2 * HH];// [W_ih2 | W_hh2] rows of 3072
__device__ __nv_bfloat16  g_whh1[WELEM];
__device__ __nv_bfloat16  g_woutb[WOUT_ELEMS];         // bf16 head
__device__ float          g_c1[2][HH];
__device__ float          g_c2[HH];
__device__ float          g_h2[2][HH];
__device__ float          g_g1[2][G4];                 // W_hh1 @ h1(t), double buffered
__device__ unsigned       g_bar;

// fast activations (cell path); softmax path uses exact expf/logf
__device__ __forceinline__ float fsigm(float x) {
    return __fdividef(1.0f, 1.0f + __expf(-x));
}
__device__ __forceinline__ float ftanh(float x) {
    x = fminf(fmaxf(x, -15.0f), 15.0f);
    float e = __expf(2.0f * x);
    return __fdividef(e - 1.0f, e + 1.0f);
}

__device__ __forceinline__ float warpsum(float v) {
    #pragma unroll
    for (int o = 16; o; o >>= 1) v += __shfl_down_sync(0xffffffffu, v, o);
    return v;
}

// NR consecutive bf16 rows (stride 'stride' elems), one shared pass over sv.
// SEGS segments of 256 elems (8 per lane). fp32 accumulate.
template<int NR, int SEGS>
__device__ __forceinline__ void dotN(const __nv_bfloat16* __restrict__ base,
                                     size_t stride, const float* __restrict__ sv,
                                     int lane, float* acc) {
    #pragma unroll
    for (int r = 0; r < NR; r++) acc[r] = 0.f;
    #pragma unroll
    for (int j = 0; j < SEGS; j++) {
        int seg = lane + 32 * j;
        const float4* v = (const float4*)(sv + seg * 8);
        float4 v0 = v[0], v1 = v[1];
        #pragma unroll
        for (int r = 0; r < NR; r++) {
            uint4 a = __ldg((const uint4*)(base + r * stride) + seg);
            float2 p;
            p = __bfloat1622float2(*(const __nv_bfloat162*)&a.x);
            acc[r] = fmaf(p.x, v0.x, acc[r]); acc[r] = fmaf(p.y, v0.y, acc[r]);
            p = __bfloat1622float2(*(const __nv_bfloat162*)&a.y);
            acc[r] = fmaf(p.x, v0.z, acc[r]); acc[r] = fmaf(p.y, v0.w, acc[r]);
            p = __bfloat1622float2(*(const __nv_bfloat162*)&a.z);
            acc[r] = fmaf(p.x, v1.x, acc[r]); acc[r] = fmaf(p.y, v1.y, acc[r]);
            p = __bfloat1622float2(*(const __nv_bfloat162*)&a.w);
            acc[r] = fmaf(p.x, v1.z, acc[r]); acc[r] = fmaf(p.y, v1.w, acc[r]);
        }
    }
}

// grid-wide barrier: cumulative counter, release/acquire fenced
__device__ __forceinline__ void grid_sync(unsigned target) {
    __threadfence();
    __syncthreads();
    if (threadIdx.x == 0) {
        atomicAdd(&g_bar, 1u);
        while (*(volatile unsigned*)&g_bar < target) { }
        __threadfence();
    }
    __syncthreads();
}

// ---------------- init ----------------
__global__ void init_kernel(const float* __restrict__ b_ih2,
                            const float* __restrict__ b_hh2) {
    int tid = threadIdx.x;  // 1024
    if (tid == 0) g_bar = 0u;
    for (int i = tid; i < HH; i += 1024) {
        g_c2[i]    = 0.0f;
        g_h2[0][i] = 0.0f;   // h2(-1)
    }
    for (int i = tid; i < G4; i += 1024) g_b2sum[i] = b_ih2[i] + b_hh2[i];
}

// ---------------- fp32 -> bf16 (rows of HH, remapped to dst_stride) ----------
__global__ void __launch_bounds__(256)
cvt_kernel(const float* __restrict__ src, __nv_bfloat16* __restrict__ dst,
           int dst_stride, int col_off, long nelem) {
    long i = ((long)blockIdx.x * 256 + threadIdx.x) * 8;
    if (i >= nelem) return;
    long row = i / HH, col = i % HH;
    float4 a = *(const float4*)(src + i);
    float4 b = *(const float4*)(src + i + 4);
    __nv_bfloat162 r0 = __floats2bfloat162_rn(a.x, a.y);
    __nv_bfloat162 r1 = __floats2bfloat162_rn(a.z, a.w);
    __nv_bfloat162 r2 = __floats2bfloat162_rn(b.x, b.y);
    __nv_bfloat162 r3 = __floats2bfloat162_rn(b.z, b.w);
    uint4 o;
    o.x = *(const unsigned*)&r0; o.y = *(const unsigned*)&r1;
    o.z = *(const unsigned*)&r2; o.w = *(const unsigned*)&r3;
    *(uint4*)(dst + row * (size_t)dst_stride + col_off + col) = o;
}

// ---------------- precompute xproj = W_ih1 @ emb^T + biases ----------------
__global__ void __launch_bounds__(512)
xproj_kernel(const float* __restrict__ Wih1,
             const float* __restrict__ bih1, const float* __restrict__ bhh1,
             const float* __restrict__ emb) {
    __shared__ __align__(16) float W[16 * E];
    int b   = blockIdx.x;
    int tid = threadIdx.x;
    for (int i = tid; i < 16 * E; i += 512)
        W[i] = Wih1[(size_t)b * 16 * E + i];
    __syncthreads();
    for (int o = tid; o < 16 * NV; o += 512) {
        int r = o & 15, v = o >> 4;
        const float4* ev = (const float4*)(emb + (size_t)v * E);
        const float4* wr = (const float4*)(W + r * E);
        float acc = 0.f;
        #pragma unroll 4
        for (int k = 0; k < E / 4; k++) {
            float4 a = wr[k], c = ev[k];
            acc = fmaf(a.x, c.x, acc); acc = fmaf(a.y, c.y, acc);
            acc = fmaf(a.z, c.z, acc); acc = fmaf(a.w, c.w, acc);
        }
        int row = b * 16 + r;
        g_xproj[(size_t)v * G4 + row] = acc + bih1[row] + bhh1[row];
    }
}

// ---------------- persistent controller: ONE barrier per step ----------------
__global__ void __launch_bounds__(NT, 1)
nas_persist(const int*   __restrict__ input_id,
            const float* __restrict__ bout,
            float* __restrict__ out) {
    __shared__ __align__(16) float sV[2 * HH];   // [h1(t) ; h2(t-1)]
    __shared__ float sG[48];
    __shared__ float sL[SS];
    __shared__ int   sId;

    const int tid  = threadIdx.x;
    const int w    = tid >> 5;
    const int lane = tid & 31;
    const int b    = blockIdx.x;
    const int u0   = b * UPB;

    for (int t = 0; t < TT; t++) {
        const int par = t & 1;   // read buffers = par, write buffers = par^1

        if (t == 0) {
            int id0 = *input_id;
            const float* xp = g_xproj + (size_t)id0 * G4;
            #pragma unroll
            for (int k = 0; k < 3; k++) {
                int u = tid + k * NT;
                float gi = xp[u], gg = xp[2 * HH + u], go = xp[3 * HH + u];
                float cn = fsigm(gi) * ftanh(gg);            // c_old = 0
                sV[u] = fsigm(go) * ftanh(cn);
                if (u >= u0 && u < u0 + UPB) g_c1[1][u] = cn;
                sV[HH + u] = 0.f;                             // h2(-1) = 0
            }
        } else {
            // prefetch (independent of argmax): h2(t-1), g1(t-1), c1(t-1)
            float hh[3], a0[3], a1[3], a2[3], a3[3], cc[3];
            #pragma unroll
            for (int k = 0; k < 3; k++) {
                int u = tid + k * NT;
                hh[k] = g_h2[par][u];
                a0[k] = g_g1[par][u];          a1[k] = g_g1[par][HH + u];
                a2[k] = g_g1[par][2 * HH + u]; a3[k] = g_g1[par][3 * HH + u];
                cc[k] = g_c1[par][u];
            }
            #pragma unroll
            for (int k = 0; k < 3; k++) sV[HH + tid + k * NT] = hh[k];
            __syncthreads();

            // logits(t-1): 2 bf16 head rows per warp, redundant per block
            {
                float acc[2];
                const __nv_bfloat16* base =
                    g_woutb + ((size_t)(t - 1) * SS + 2 * w) * HH;
                dotN<2, 6>(base, HH, sV + HH, lane, acc);
                acc[0] = warpsum(acc[0]);
                acc[1] = warpsum(acc[1]);
                if (lane == 0) {
                    sL[2 * w]     = acc[0] + bout[(t - 1) * SS + 2 * w];
                    sL[2 * w + 1] = acc[1] + bout[(t - 1) * SS + 2 * w + 1];
                }
            }
            __syncthreads();

            if (w == 0) {   // exact log_softmax + argmax (first-index tie-break)
                float v = sL[lane];
                float m = v;
                #pragma unroll
                for (int o = 16; o; o >>= 1) m = fmaxf(m, __shfl_xor_sync(0xffffffffu, m, o));
                float e = expf(v - m), se = e;
                #pragma unroll
                for (int o = 16; o; o >>= 1) se += __shfl_xor_sync(0xffffffffu, se, o);
                float lse = m + logf(se);
                if (b == 0) out[(t - 1) * SS + lane] = v - lse;
                float bv = v; int bi = lane;
                #pragma unroll
                for (int o = 16; o; o >>= 1) {
                    float ov = __shfl_xor_sync(0xffffffffu, bv, o);
                    int   oi = __shfl_xor_sync(0xffffffffu, bi, o);
                    if (ov > bv || (ov == bv && oi < bi)) { bv = ov; bi = oi; }
                }
                if (lane == 0) sId = ((t - 1) & 3) * SS + bi;
            }
            __syncthreads();

            // build full h1(t) redundantly; update own c1 units
            const float* xp = g_xproj + (size_t)sId * G4;
            #pragma unroll
            for (int k = 0; k < 3; k++) {
                int u = tid + k * NT;
                float gi = a0[k] + xp[u];
                float gf = a1[k] + xp[HH + u];
                float gg = a2[k] + xp[2 * HH + u];
                float go = a3[k] + xp[3 * HH + u];
                float cn = fsigm(gf) * cc[k] + fsigm(gi) * ftanh(gg);
                sV[u] = fsigm(go) * ftanh(cn);
                if (u >= u0 && u < u0 + UPB) g_c1[par ^ 1][u] = cn;
            }
        }
        __syncthreads();

        // cell2 gates: 3 consecutive concat rows (3072) per warp, one pass
        {
            int gate = w >> 2;
            int j0   = (w & 3) * 3;
            int grow = gate * HH + u0 + j0;
            float acc[3];
            dotN<3, 12>(g_w2cat + (size_t)grow * (2 * HH), 2 * HH, sV, lane, acc);
            #pragma unroll
            for (int q = 0; q < 3; q++) acc[q] = warpsum(acc[q]);
            if (lane == 0) {
                sG[gate * 12 + j0]     = acc[0] + g_b2sum[grow];
                sG[gate * 12 + j0 + 1] = acc[1] + g_b2sum[grow + 1];
                sG[gate * 12 + j0 + 2] = acc[2] + g_b2sum[grow + 2];
            }
        }
        // g1(t) = W_hh1 @ h1(t): 3 consecutive rows per warp, distributed
        {
            int row = b * 48 + w * 3;
            float acc[3];
            dotN<3, 6>(g_whh1 + (size_t)row * HH, HH, sV, lane, acc);
            #pragma unroll
            for (int q = 0; q < 3; q++) acc[q] = warpsum(acc[q]);
            if (lane == 0) {
                g_g1[par ^ 1][row]     = acc[0];
                g_g1[par ^ 1][row + 1] = acc[1];
                g_g1[par ^ 1][row + 2] = acc[2];
            }
        }
        __syncthreads();

        if (tid < UPB) {
            int u = u0 + tid;
            float gi = sG[tid], gf = sG[12 + tid], gg = sG[24 + tid], go = sG[36 + tid];
            float c  = g_c2[u];
            float cn = fsigm(gf) * c + fsigm(gi) * ftanh(gg);
            g_c2[u]          = cn;
            g_h2[par ^ 1][u] = fsigm(go) * ftanh(cn);
        }
        grid_sync((unsigned)(t + 1) * NB);
    }

    // epilogue: logits(47) from h2(47) (in g_h2[0]); block 0 only
    if (b == 0) {
        #pragma unroll
        for (int k = 0; k < 3; k++) {
            int u = tid + k * NT;
            sV[HH + u] = g_h2[0][u];
        }
        __syncthreads();
        float acc[2];
        const __nv_bfloat16* base = g_woutb + ((size_t)47 * SS + 2 * w) * HH;
        dotN<2, 6>(base, HH, sV + HH, lane, acc);
        acc[0] = warpsum(acc[0]);
        acc[1] = warpsum(acc[1]);
        if (lane == 0) {
            sL[2 * w]     = acc[0] + bout[47 * SS + 2 * w];
            sL[2 * w + 1] = acc[1] + bout[47 * SS + 2 * w + 1];
        }
        __syncthreads();
        if (w == 0) {
            float v = sL[lane];
            float m = v;
            #pragma unroll
            for (int o = 16; o; o >>= 1) m = fmaxf(m, __shfl_xor_sync(0xffffffffu, m, o));
            float e = expf(v - m), se = e;
            #pragma unroll
            for (int o = 16; o; o >>= 1) se += __shfl_xor_sync(0xffffffffu, se, o);
            float lse = m + logf(se);
            out[47 * SS + lane] = v - lse;
        }
    }
}

extern "C" void kernel_launch(void* const* d_in, const int* in_sizes, int n_in,
                              void* d_out, int out_size) {
    const int*   input_id = (const int*)  d_in[0];
    const float* emb      = (const float*)d_in[1];
    const float* W_ih1    = (const float*)d_in[2];
    const float* W_hh1    = (const float*)d_in[3];
    const float* b_ih1    = (const float*)d_in[4];
    const float* b_hh1    = (const float*)d_in[5];
    const float* W_ih2    = (const float*)d_in[6];
    const float* W_hh2    = (const float*)d_in[7];
    const float* b_ih2    = (const float*)d_in[8];
    const float* b_hh2    = (const float*)d_in[9];
    const float* W_out    = (const float*)d_in[10];
    const float* b_out    = (const float*)d_in[11];
    float* out = (float*)d_out;

    __nv_bfloat16* w2cat_d; cudaGetSymbolAddress((void**)&w2cat_d, g_w2cat);
    __nv_bfloat16* whh1_d;  cudaGetSymbolAddress((void**)&whh1_d,  g_whh1);
    __nv_bfloat16* woutb_d; cudaGetSymbolAddress((void**)&woutb_d, g_woutb);

    const int cvtW = (WELEM / 8 + 255) / 256;
    const int cvtO = (WOUT_ELEMS / 8 + 255) / 256;
    init_kernel<<<1, 1024>>>(b_ih2, b_hh2);
    cvt_kernel<<<cvtW, 256>>>(W_ih2, w2cat_d, 2 * HH, 0,  WELEM);
    cvt_kernel<<<cvtW, 256>>>(W_hh2, w2cat_d, 2 * HH, HH, WELEM);
    cvt_kernel<<<cvtW, 256>>>(W_hh1, whh1_d, HH, 0, WELEM);
    cvt_kernel<<<cvtO, 256>>>(W_out, woutb_d, HH, 0, WOUT_ELEMS);
    xproj_kernel<<<G4 / 16, 512>>>(W_ih1, b_ih1, b_hh1, emb);
    nas_persist<<<NB, NT>>>(input_id, b_out, out);
}